// round 2
// baseline (speedup 1.0000x reference)
#include <cuda_runtime.h>
#include <cstdint>

// ============================================================================
// NCMOpenMax: probas = softmax(cos(X, muK), axis=1)
//   X [262144,128] f32, muK [512,128] f32, out [262144,512] f32
//
// No tcgen05 (harness PTX target is plain sm_103). Strategy:
//   prep kernel: normalize muK, convert to tf32, scatter into
//                mma-fragment-ordered global array g_bfrag.
//   main kernel: CTA = 64 rows x 512 classes, mma.sync.m16n8k8.tf32,
//                cp.async double-buffered K-chunks, fused softmax epilogue
//                (shift by 1 since cos<=1 -> exact softmax, no max pass).
// ============================================================================

static constexpr int DDIM = 128;   // feature dim (GEMM K)
static constexpr int KCLS = 512;   // classes (GEMM N)
static constexpr int BM   = 64;    // rows per CTA

// B fragments: [chunk c(4)][kstep s(4)][ntile t(64)][lane(32)] x float2
__device__ float2 g_bfrag[4 * 4 * 64 * 32];   // 256 KB

// ---- smem layout (bytes, dynamic) ----
static constexpr int SMEM_B0   = 0;          // 64 KB
static constexpr int SMEM_B1   = 65536;      // 64 KB
static constexpr int SMEM_A0   = 131072;     // 64*36*4 = 9216 B
static constexpr int SMEM_A1   = 140288;     // 9216 B
static constexpr int SMEM_NORM = 149504;     // 64 floats
static constexpr int SMEM_RS   = 149760;     // 2*64 floats
static constexpr int SMEM_TOTAL = 150272;

__device__ __forceinline__ uint32_t f2tf32(float f) {
    uint32_t r;
    asm("cvt.rna.tf32.f32 %0, %1;" : "=r"(r) : "f"(f));
    return r;
}

__device__ __forceinline__ void mma_tf32(float* d, const uint32_t* a,
                                         uint32_t b0, uint32_t b1) {
    asm volatile(
        "mma.sync.aligned.m16n8k8.row.col.f32.tf32.tf32.f32 "
        "{%0,%1,%2,%3}, {%4,%5,%6,%7}, {%8,%9}, {%0,%1,%2,%3};"
        : "+f"(d[0]), "+f"(d[1]), "+f"(d[2]), "+f"(d[3])
        : "r"(a[0]), "r"(a[1]), "r"(a[2]), "r"(a[3]), "r"(b0), "r"(b1));
}

#define CP_ASYNC16(dst_u32, src_ptr) \
    asm volatile("cp.async.cg.shared.global [%0], [%1], 16;" \
                 :: "r"(dst_u32), "l"(src_ptr) : "memory")
#define CP_COMMIT() asm volatile("cp.async.commit_group;" ::: "memory")

__device__ __forceinline__ uint32_t smem_u32(const void* p) {
    uint32_t a;
    asm("{ .reg .u64 t; cvta.to.shared.u64 t, %1; cvt.u32.u64 %0, t; }"
        : "=r"(a) : "l"(p));
    return a;
}

// ---------------- prep: normalize muK -> tf32 fragment order ----------------

__global__ void ncm_prep_kernel(const float* __restrict__ muK) {
    __shared__ float p[4];
    int n = blockIdx.x;          // class
    int k = threadIdx.x;         // feature
    float v = muK[n * DDIM + k];
    float ss = v * v;
    #pragma unroll
    for (int o = 16; o > 0; o >>= 1)
        ss += __shfl_xor_sync(0xffffffffu, ss, o);
    if ((k & 31) == 0) p[k >> 5] = ss;
    __syncthreads();
    float inv = 1.0f / fmaxf(sqrtf(p[0] + p[1] + p[2] + p[3]), 1e-8f);
    uint32_t bits = f2tf32(v * inv);

    // fragment position for mma.m16n8k8 .col B operand:
    //   b0: (k'=lane&3,  n'=lane>>2), b1: (k'=(lane&3)+4, n'=lane>>2)
    int c  = k >> 5;            // 32-feature chunk
    int s  = (k >> 3) & 3;      // k8 step within chunk
    int k7 = k & 7;             // position within k8
    int t  = n >> 3;            // 8-class n-tile
    int l  = (n & 7) * 4 + (k7 & 3);
    int idx = ((c * 4 + s) * 64 + t) * 32 + l;
    reinterpret_cast<float*>(&g_bfrag[idx])[k7 >> 2] = __uint_as_float(bits);
}

// ---------------- main: GEMM + fused softmax ----------------

__global__ void __launch_bounds__(256, 1)
ncm_main_kernel(const float* __restrict__ X, float* __restrict__ out) {
    extern __shared__ char smem[];
    const uint32_t sb = smem_u32(smem);

    const int tid  = threadIdx.x;
    const int lane = tid & 31;
    const int wid  = tid >> 5;
    const int wr   = wid & 3;    // warp row (16-row slab)
    const int wc   = wid >> 2;   // warp col (256-class half)
    const int g    = lane >> 2;
    const int kq   = lane & 3;
    const size_t row_base = (size_t)blockIdx.x * BM;

    // ---- per-row inverse norms (4 threads per row, 32 floats each) ----
    {
        int r = tid >> 2, q = tid & 3;
        const float4* src = reinterpret_cast<const float4*>(
            X + (row_base + r) * DDIM + q * 32);
        float ss = 0.f;
        #pragma unroll
        for (int i = 0; i < 8; i++) {
            float4 v = src[i];
            ss += v.x * v.x + v.y * v.y + v.z * v.z + v.w * v.w;
        }
        ss += __shfl_xor_sync(0xffffffffu, ss, 1);
        ss += __shfl_xor_sync(0xffffffffu, ss, 2);
        if (q == 0)
            reinterpret_cast<float*>(smem + SMEM_NORM)[r] =
                1.0f / fmaxf(sqrtf(ss), 1e-8f);
    }

    const uint32_t boff[2] = {sb + SMEM_B0, sb + SMEM_B1};
    const uint32_t aoff[2] = {sb + SMEM_A0, sb + SMEM_A1};

    auto load_chunk = [&](int c, int buf) {
        // B fragments: contiguous 64 KB, 16 x 16B per thread
        const char* bsrc = reinterpret_cast<const char*>(g_bfrag) + c * 65536;
        #pragma unroll
        for (int i = 0; i < 16; i++) {
            uint32_t o = (uint32_t)(i * 4096 + tid * 16);
            CP_ASYNC16(boff[buf] + o, bsrc + o);
        }
        // A tile: 64 rows x 32 floats, padded stride 36 floats
        #pragma unroll
        for (int i = 0; i < 2; i++) {
            int e = tid + i * 256;
            int r = e >> 3, q = e & 7;
            const float* asrc = X + (row_base + r) * DDIM + c * 32 + q * 4;
            uint32_t adst = aoff[buf] + (uint32_t)(r * 36 + q * 4) * 4;
            CP_ASYNC16(adst, asrc);
        }
    };

    load_chunk(0, 0);
    CP_COMMIT();

    float acc[128];
    #pragma unroll
    for (int i = 0; i < 128; i++) acc[i] = 0.f;

    #pragma unroll
    for (int c = 0; c < 4; c++) {
        if (c < 3) {
            load_chunk(c + 1, (c + 1) & 1);
            CP_COMMIT();
            asm volatile("cp.async.wait_group 1;" ::: "memory");
        } else {
            asm volatile("cp.async.wait_group 0;" ::: "memory");
        }
        __syncthreads();

        const float*  As = reinterpret_cast<const float*>(smem) +
                           (c & 1 ? SMEM_A1 : SMEM_A0) / 4;
        const float2* Bs = reinterpret_cast<const float2*>(
                           smem + (c & 1 ? SMEM_B1 : SMEM_B0));

        #pragma unroll
        for (int s = 0; s < 4; s++) {
            uint32_t a[4];
            int r0 = (wr * 16 + g) * 36 + s * 8 + kq;
            a[0] = f2tf32(As[r0]);
            a[1] = f2tf32(As[r0 + 8 * 36]);
            a[2] = f2tf32(As[r0 + 4]);
            a[3] = f2tf32(As[r0 + 8 * 36 + 4]);
            #pragma unroll
            for (int j = 0; j < 32; j++) {
                int t = wc * 32 + j;
                float2 b = Bs[(s * 64 + t) * 32 + lane];
                mma_tf32(&acc[j * 4], a,
                         __float_as_uint(b.x), __float_as_uint(b.y));
            }
        }
        __syncthreads();
    }

    // ---- fused softmax epilogue ----
    const int row0 = wr * 16 + g;
    const int row1 = row0 + 8;
    const float* norms = reinterpret_cast<const float*>(smem + SMEM_NORM);
    const float in0 = norms[row0];
    const float in1 = norms[row1];

    float s0 = 0.f, s1 = 0.f;
    #pragma unroll
    for (int j = 0; j < 32; j++) {
        float e0 = __expf(acc[j * 4 + 0] * in0 - 1.0f);
        float e1 = __expf(acc[j * 4 + 1] * in0 - 1.0f);
        float e2 = __expf(acc[j * 4 + 2] * in1 - 1.0f);
        float e3 = __expf(acc[j * 4 + 3] * in1 - 1.0f);
        acc[j * 4 + 0] = e0; acc[j * 4 + 1] = e1;
        acc[j * 4 + 2] = e2; acc[j * 4 + 3] = e3;
        s0 += e0 + e1;
        s1 += e2 + e3;
    }
    s0 += __shfl_xor_sync(0xffffffffu, s0, 1);
    s0 += __shfl_xor_sync(0xffffffffu, s0, 2);
    s1 += __shfl_xor_sync(0xffffffffu, s1, 1);
    s1 += __shfl_xor_sync(0xffffffffu, s1, 2);

    float* rs = reinterpret_cast<float*>(smem + SMEM_RS);
    if ((lane & 3) == 0) {
        rs[wc * 64 + row0] = s0;
        rs[wc * 64 + row1] = s1;
    }
    __syncthreads();
    const float v0 = 1.0f / (rs[row0] + rs[64 + row0]);
    const float v1 = 1.0f / (rs[row1] + rs[64 + row1]);

    float2* o0 = reinterpret_cast<float2*>(
        out + (row_base + row0) * KCLS + wc * 256 + 2 * kq);
    float2* o1 = reinterpret_cast<float2*>(
        out + (row_base + row1) * KCLS + wc * 256 + 2 * kq);
    #pragma unroll
    for (int j = 0; j < 32; j++) {
        o0[j * 4] = make_float2(acc[j * 4 + 0] * v0, acc[j * 4 + 1] * v0);
        o1[j * 4] = make_float2(acc[j * 4 + 2] * v1, acc[j * 4 + 3] * v1);
    }
}

// ---------------- launch ----------------

extern "C" void kernel_launch(void* const* d_in, const int* in_sizes, int n_in,
                              void* d_out, int out_size) {
    const float* X   = (const float*)d_in[0];   // [N,128]
    const float* muK = (const float*)d_in[1];   // [512,128]
    float* out = (float*)d_out;                 // [N,512]

    int N = in_sizes[0] / DDIM;
    int tiles = N / BM;  // 4096

    static bool attr_set = false;
    cudaFuncSetAttribute(ncm_main_kernel,
                         cudaFuncAttributeMaxDynamicSharedMemorySize,
                         SMEM_TOTAL);
    (void)attr_set;

    ncm_prep_kernel<<<KCLS, DDIM>>>(muK);
    ncm_main_kernel<<<tiles, 256, SMEM_TOTAL>>>(X, out);
}

// round 3
// speedup vs baseline: 1.6323x; 1.6323x over previous
#include <cuda_runtime.h>
#include <cuda_fp16.h>
#include <cstdint>

// ============================================================================
// NCMOpenMax: probas = softmax(cos(X, muK), axis=1)
//   X [262144,128] f32, muK [512,128] f32, out [262144,512] f32
//
// fp16 mma.sync.m16n8k16, persistent CTAs, whole B resident in smem,
// double-buffered A (LDG f32 -> cvt f16 -> STS), fused softmax (cos<=1 =>
// fixed shift exp(s-1), exact softmax, no max pass).
// ============================================================================

static constexpr int DDIM = 128;
static constexpr int KCLS = 512;
static constexpr int BM   = 64;

// B fragments, fp16, mma-fragment order: [s(8)][t(64)][lane(32)][4 halves]
__device__ __half g_bfrag[8 * 64 * 32 * 4];   // 128 KB

// ---- smem layout (bytes) ----
static constexpr int SM_B      = 0;                      // 131072
static constexpr int A_STRIDE  = 272;                    // 136 halves/row (pad 8)
static constexpr int A_BYTES   = BM * A_STRIDE;          // 17408
static constexpr int SM_A0     = 131072;
static constexpr int SM_A1     = SM_A0 + A_BYTES;        // 148480
static constexpr int SM_NRM    = SM_A1 + A_BYTES;        // 165888 (2 x 64 f32)
static constexpr int SM_RS     = SM_NRM + 512;           // 166400 (8 x 64 f32)
static constexpr int SM_INV    = SM_RS + 2048;           // 168448 (64 f32)
static constexpr int SM_TOTAL  = SM_INV + 256;           // 168704

__device__ __forceinline__ uint32_t smem_u32(const void* p) {
    uint32_t a;
    asm("{ .reg .u64 t; cvta.to.shared.u64 t, %1; cvt.u32.u64 %0, t; }"
        : "=r"(a) : "l"(p));
    return a;
}

#define CP_ASYNC16(dst_u32, src_ptr) \
    asm volatile("cp.async.cg.shared.global [%0], [%1], 16;" \
                 :: "r"(dst_u32), "l"(src_ptr) : "memory")

__device__ __forceinline__ void mma_f16(float* d, const uint32_t* a,
                                        uint32_t b0, uint32_t b1) {
    asm volatile(
        "mma.sync.aligned.m16n8k16.row.col.f32.f16.f16.f32 "
        "{%0,%1,%2,%3},{%4,%5,%6,%7},{%8,%9},{%0,%1,%2,%3};"
        : "+f"(d[0]), "+f"(d[1]), "+f"(d[2]), "+f"(d[3])
        : "r"(a[0]), "r"(a[1]), "r"(a[2]), "r"(a[3]), "r"(b0), "r"(b1));
}

// ---------------- prep: normalize muK -> fp16 fragment order ----------------

__global__ void ncm_prep(const float* __restrict__ muK) {
    __shared__ float pp[4];
    int n = blockIdx.x;       // class
    int k = threadIdx.x;      // feature
    float v = muK[n * DDIM + k];
    float ss = v * v;
    #pragma unroll
    for (int o = 16; o > 0; o >>= 1)
        ss += __shfl_xor_sync(0xffffffffu, ss, o);
    if ((k & 31) == 0) pp[k >> 5] = ss;
    __syncthreads();
    float inv = 1.0f / fmaxf(sqrtf(pp[0] + pp[1] + pp[2] + pp[3]), 1e-8f);

    // m16n8k16 .col B fragment: b0: k=2*(lane&3)+{0,1}; b1: k+8; n=lane>>2
    int s    = k >> 4;
    int kk   = k & 15;
    int t    = n >> 3;
    int lane = (n & 7) * 4 + ((kk & 7) >> 1);
    int idx  = ((kk >= 8) ? 2 : 0) + (kk & 1);
    g_bfrag[(((s * 64 + t) * 32 + lane) << 2) + idx] = __float2half_rn(v * inv);
}

// ---------------- main: persistent GEMM + fused softmax ----------------

__global__ void __launch_bounds__(256, 1)
ncm_main(const float* __restrict__ X, float* __restrict__ out, int tiles) {
    extern __shared__ char smem[];
    const uint32_t sb = smem_u32(smem);
    const int tid  = threadIdx.x;
    const int lane = tid & 31;
    const int wid  = tid >> 5;
    const int g    = lane >> 2;
    const int kq   = lane & 3;

    // ldmatrix lane addressing: matrix m = lane>>3, row-in-matrix rr = lane&7
    const int m_    = lane >> 3;
    const int lrow  = ((m_ & 1) << 3) + (lane & 7);
    const int lkoff = (m_ >> 1) << 4;

    // ---- load whole B (128 KB) once ----
    {
        const char* bsrc = reinterpret_cast<const char*>(g_bfrag);
        #pragma unroll
        for (int i = 0; i < 32; i++) {
            uint32_t o = (uint32_t)(i * 4096 + tid * 16);
            CP_ASYNC16(sb + SM_B + o, bsrc + o);
        }
        asm volatile("cp.async.commit_group;" ::: "memory");
    }

    const int r = tid >> 2;   // A row owned for load path
    const int q = tid & 3;    // 32-float quarter of that row
    int tile = blockIdx.x;

    // ---- preamble: A(tile0) into buf0 + norms ----
    {
        const float4* src = reinterpret_cast<const float4*>(
            X + ((size_t)tile * BM + r) * DDIM + q * 32);
        float4 x[8];
        #pragma unroll
        for (int i = 0; i < 8; i++) x[i] = src[i];
        float ss = 0.f;
        #pragma unroll
        for (int i = 0; i < 8; i++)
            ss += x[i].x * x[i].x + x[i].y * x[i].y +
                  x[i].z * x[i].z + x[i].w * x[i].w;
        ss += __shfl_xor_sync(0xffffffffu, ss, 1);
        ss += __shfl_xor_sync(0xffffffffu, ss, 2);
        if (q == 0)
            reinterpret_cast<float*>(smem + SM_NRM)[r] =
                1.0f / fmaxf(sqrtf(ss), 1e-8f);
        char* adst = smem + SM_A0 + r * A_STRIDE + q * 64;
        #pragma unroll
        for (int i = 0; i < 8; i++) {
            __half2 h0 = __floats2half2_rn(x[i].x, x[i].y);
            __half2 h1 = __floats2half2_rn(x[i].z, x[i].w);
            uint2 u;
            u.x = *reinterpret_cast<uint32_t*>(&h0);
            u.y = *reinterpret_cast<uint32_t*>(&h1);
            *reinterpret_cast<uint2*>(adst + i * 8) = u;
        }
    }
    asm volatile("cp.async.wait_group 0;" ::: "memory");
    __syncthreads();

    const uint2* Bs   = reinterpret_cast<const uint2*>(smem + SM_B);
    float* rs_arr     = reinterpret_cast<float*>(smem + SM_RS);
    float* inv_arr    = reinterpret_cast<float*>(smem + SM_INV);

    int p = 0;
    while (tile < tiles) {
        const int tnext = tile + gridDim.x;
        const bool hn = tnext < tiles;

        // prefetch next A into regs (latency hidden under mma phase)
        float4 x[8];
        if (hn) {
            const float4* src = reinterpret_cast<const float4*>(
                X + ((size_t)tnext * BM + r) * DDIM + q * 32);
            #pragma unroll
            for (int i = 0; i < 8; i++) x[i] = src[i];
        }

        float acc[4][8][4];
        #pragma unroll
        for (int sl = 0; sl < 4; sl++)
            #pragma unroll
            for (int t = 0; t < 8; t++)
                #pragma unroll
                for (int c = 0; c < 4; c++) acc[sl][t][c] = 0.f;

        // ---- mma phase: warp = 64 rows x 64 cols ----
        const uint32_t abase = sb + (p ? SM_A1 : SM_A0);
        #pragma unroll
        for (int s = 0; s < 8; s++) {
            uint32_t a[4][4];
            #pragma unroll
            for (int sl = 0; sl < 4; sl++) {
                uint32_t addr = abase + (uint32_t)((sl * 16 + lrow) * A_STRIDE
                                                   + s * 32 + lkoff);
                asm volatile(
                    "ldmatrix.sync.aligned.m8n8.x4.shared.b16 {%0,%1,%2,%3},[%4];"
                    : "=r"(a[sl][0]), "=r"(a[sl][1]),
                      "=r"(a[sl][2]), "=r"(a[sl][3])
                    : "r"(addr));
            }
            #pragma unroll
            for (int t = 0; t < 8; t++) {
                uint2 b = Bs[(s * 64 + wid * 8 + t) * 32 + lane];
                #pragma unroll
                for (int sl = 0; sl < 4; sl++)
                    mma_f16(acc[sl][t], a[sl], b.x, b.y);
            }
        }

        // ---- stage next A (cvt + STS) + next norms ----
        if (hn) {
            float ss = 0.f;
            #pragma unroll
            for (int i = 0; i < 8; i++)
                ss += x[i].x * x[i].x + x[i].y * x[i].y +
                      x[i].z * x[i].z + x[i].w * x[i].w;
            ss += __shfl_xor_sync(0xffffffffu, ss, 1);
            ss += __shfl_xor_sync(0xffffffffu, ss, 2);
            if (q == 0)
                reinterpret_cast<float*>(smem + SM_NRM)[(p ^ 1) * 64 + r] =
                    1.0f / fmaxf(sqrtf(ss), 1e-8f);
            char* adst = smem + (p ? SM_A0 : SM_A1) + r * A_STRIDE + q * 64;
            #pragma unroll
            for (int i = 0; i < 8; i++) {
                __half2 h0 = __floats2half2_rn(x[i].x, x[i].y);
                __half2 h1 = __floats2half2_rn(x[i].z, x[i].w);
                uint2 u;
                u.x = *reinterpret_cast<uint32_t*>(&h0);
                u.y = *reinterpret_cast<uint32_t*>(&h1);
                *reinterpret_cast<uint2*>(adst + i * 8) = u;
            }
        }

        // ---- epilogue pass 1: exp, partial row sums ----
        const float* nrmc = reinterpret_cast<const float*>(smem + SM_NRM) + p * 64;
        #pragma unroll
        for (int sl = 0; sl < 4; sl++) {
            #pragma unroll
            for (int h = 0; h < 2; h++) {
                const int row = sl * 16 + h * 8 + g;
                const float nv = nrmc[row];
                float psum = 0.f;
                #pragma unroll
                for (int t = 0; t < 8; t++) {
                    float e0 = __expf(acc[sl][t][h * 2 + 0] * nv - 1.0f);
                    float e1 = __expf(acc[sl][t][h * 2 + 1] * nv - 1.0f);
                    acc[sl][t][h * 2 + 0] = e0;
                    acc[sl][t][h * 2 + 1] = e1;
                    psum += e0 + e1;
                }
                psum += __shfl_xor_sync(0xffffffffu, psum, 1);
                psum += __shfl_xor_sync(0xffffffffu, psum, 2);
                if (kq == 0) rs_arr[wid * 64 + row] = psum;
            }
        }
        __syncthreads();

        if (tid < 64) {
            float s = 0.f;
            #pragma unroll
            for (int w = 0; w < 8; w++) s += rs_arr[w * 64 + tid];
            inv_arr[tid] = 1.0f / s;
        }
        __syncthreads();

        // ---- epilogue pass 2: scale + store ----
        #pragma unroll
        for (int sl = 0; sl < 4; sl++) {
            #pragma unroll
            for (int h = 0; h < 2; h++) {
                const int row = sl * 16 + h * 8 + g;
                const float iv = inv_arr[row];
                float* op = out + ((size_t)tile * BM + row) * KCLS
                                + wid * 64 + kq * 2;
                #pragma unroll
                for (int t = 0; t < 8; t++) {
                    float2 v = make_float2(acc[sl][t][h * 2 + 0] * iv,
                                           acc[sl][t][h * 2 + 1] * iv);
                    *reinterpret_cast<float2*>(op + t * 8) = v;
                }
            }
        }

        tile = tnext;
        p ^= 1;
    }
}

// ---------------- launch ----------------

extern "C" void kernel_launch(void* const* d_in, const int* in_sizes, int n_in,
                              void* d_out, int out_size) {
    const float* X   = (const float*)d_in[0];   // [N,128]
    const float* muK = (const float*)d_in[1];   // [512,128]
    float* out = (float*)d_out;                 // [N,512]

    static int sms = 0;
    if (!sms) {
        cudaDeviceGetAttribute(&sms, cudaDevAttrMultiProcessorCount, 0);
        if (sms <= 0) sms = 148;
        cudaFuncSetAttribute(ncm_main,
                             cudaFuncAttributeMaxDynamicSharedMemorySize,
                             SM_TOTAL);
    }

    int N = in_sizes[0] / DDIM;
    int tiles = N / BM;                 // 4096
    int grid = tiles < sms ? tiles : sms;

    ncm_prep<<<KCLS, DDIM>>>(muK);
    ncm_main<<<grid, 256, SM_TOTAL>>>(X, out, tiles);
}